// round 3
// baseline (speedup 1.0000x reference)
#include <cuda_runtime.h>

#define NN 100000
#define NE 1600000
#define NG 128
#define NF 128
#define NC 64
#define SCAN_BS 512
#define SCAN_BLOCKS ((NN + SCAN_BS - 1) / SCAN_BS)   // 196

// ---------------- scratch (static __device__ allocations: allowed) ----------------
__device__ int   g_deg_out[2][NN];
__device__ int   g_deg_in [2][NN];
__device__ int   g_off    [2][NN + 1];
__device__ int   g_cursor [2][NN];
__device__ int   g_bsums  [2][256];
__device__ int   g_esrc   [2][NE];
__device__ float g_agg    [2][NN * NF];       // 51.2 MB each
__device__ float g_gsum   [2][NG * NF];
__device__ int   g_gcnt   [2][NG];

// ---------------- small helpers ----------------
__device__ __forceinline__ unsigned long long fma2(unsigned long long a,
                                                   unsigned long long b,
                                                   unsigned long long c) {
    unsigned long long d;
    asm("fma.rn.f32x2 %0, %1, %2, %3;" : "=l"(d) : "l"(a), "l"(b), "l"(c));
    return d;
}
__device__ __forceinline__ float sum2(unsigned long long v) {
    float2 f = *reinterpret_cast<float2*>(&v);
    return f.x + f.y;
}

// ---------------- kernels ----------------
__global__ void zero_kernel(int br) {
    int i = blockIdx.x * blockDim.x + threadIdx.x;
    if (i < NN) { g_deg_out[br][i] = 0; g_deg_in[br][i] = 0; }
    if (i < NG * NF) g_gsum[br][i] = 0.f;
    if (i < NG) g_gcnt[br][i] = 0;
}

__global__ void degree_kernel(const int* __restrict__ src, const int* __restrict__ dst, int br) {
    int i = blockIdx.x * blockDim.x + threadIdx.x;
    if (i < NE) {
        atomicAdd(&g_deg_out[br][src[i]], 1);
        atomicAdd(&g_deg_in [br][dst[i]], 1);
    }
}

__global__ void hist_kernel(const int* __restrict__ gid, int br) {
    __shared__ int sh[NG];
    int tid = threadIdx.x;
    if (tid < NG) sh[tid] = 0;
    __syncthreads();
    for (int i = blockIdx.x * blockDim.x + tid; i < NN; i += gridDim.x * blockDim.x)
        atomicAdd(&sh[gid[i]], 1);
    __syncthreads();
    if (tid < NG && sh[tid]) atomicAdd(&g_gcnt[br][tid], sh[tid]);
}

__global__ void scan1_kernel(int br) {
    __shared__ int sh[SCAN_BS];
    int tid = threadIdx.x;
    int i = blockIdx.x * SCAN_BS + tid;
    int v = (i < NN) ? g_deg_in[br][i] : 0;
    sh[tid] = v;
    __syncthreads();
    for (int o = 1; o < SCAN_BS; o <<= 1) {
        int t = (tid >= o) ? sh[tid - o] : 0;
        __syncthreads();
        sh[tid] += t;
        __syncthreads();
    }
    if (i < NN) g_off[br][i + 1] = sh[tid];
    if (tid == SCAN_BS - 1) g_bsums[br][blockIdx.x] = sh[tid];
}

__global__ void scan2_kernel(int br) {
    if (threadIdx.x == 0) {
        int acc = 0;
        for (int b = 0; b < SCAN_BLOCKS; b++) {
            int t = g_bsums[br][b];
            g_bsums[br][b] = acc;
            acc += t;
        }
    }
}

__global__ void scan3_kernel(int br) {
    int i = blockIdx.x * SCAN_BS + threadIdx.x;
    if (i < NN) g_off[br][i + 1] += g_bsums[br][i >> 9];
    if (i == 0) g_off[br][0] = 0;
}

__global__ void cursor_kernel(int br) {
    int i = blockIdx.x * blockDim.x + threadIdx.x;
    if (i < NN) g_cursor[br][i] = g_off[br][i];
}

__global__ void scatter_kernel(const int* __restrict__ src, const int* __restrict__ dst, int br) {
    int i = blockIdx.x * blockDim.x + threadIdx.x;
    if (i < NE) {
        int d = dst[i];
        int p = atomicAdd(&g_cursor[br][d], 1);
        g_esrc[br][p] = src[i];
    }
}

// one warp per dst node: agg[node] = d_in^{-1/2} * sum_e feat[src_e] * d_out[src_e]^{-1/2}
__global__ __launch_bounds__(256) void agg_kernel(const float4* __restrict__ feat4, int br) {
    int warp = (blockIdx.x * 256 + threadIdx.x) >> 5;
    int lane = threadIdx.x & 31;
    if (warp >= NN) return;
    const int* __restrict__ esrc = g_esrc[br];
    const int* __restrict__ dout = g_deg_out[br];
    int beg = g_off[br][warp], end = g_off[br][warp + 1];
    float4 acc = make_float4(0.f, 0.f, 0.f, 0.f);
    int i = beg;
    for (; i + 1 < end; i += 2) {
        int s0 = esrc[i], s1 = esrc[i + 1];
        float c0 = rsqrtf(fmaxf((float)dout[s0], 1.f));
        float c1 = rsqrtf(fmaxf((float)dout[s1], 1.f));
        float4 v0 = feat4[s0 * 32 + lane];
        float4 v1 = feat4[s1 * 32 + lane];
        acc.x = fmaf(v0.x, c0, acc.x); acc.y = fmaf(v0.y, c0, acc.y);
        acc.z = fmaf(v0.z, c0, acc.z); acc.w = fmaf(v0.w, c0, acc.w);
        acc.x = fmaf(v1.x, c1, acc.x); acc.y = fmaf(v1.y, c1, acc.y);
        acc.z = fmaf(v1.z, c1, acc.z); acc.w = fmaf(v1.w, c1, acc.w);
    }
    if (i < end) {
        int s0 = esrc[i];
        float c0 = rsqrtf(fmaxf((float)dout[s0], 1.f));
        float4 v0 = feat4[s0 * 32 + lane];
        acc.x = fmaf(v0.x, c0, acc.x); acc.y = fmaf(v0.y, c0, acc.y);
        acc.z = fmaf(v0.z, c0, acc.z); acc.w = fmaf(v0.w, c0, acc.w);
    }
    float dis = rsqrtf(fmaxf((float)(end - beg), 1.f));
    acc.x *= dis; acc.y *= dis; acc.z *= dis; acc.w *= dis;
    reinterpret_cast<float4*>(g_agg[br])[warp * 32 + lane] = acc;
}

// block: 128 nodes x full 128 cols. GEMM (agg @ W) + bias + L2 norm + sigmoid + graph sums.
__global__ __launch_bounds__(256, 1) void gemm_epilogue_kernel(
        int br, const float* __restrict__ W, const float* __restrict__ bias,
        const int* __restrict__ gidv) {
    extern __shared__ float sm[];
    float* As  = sm;            // [128][128] row-major (node-row, k)
    float* Wst = sm + 16384;    // [128 j][130] k-contiguous (transposed W, padded)
    const int tid = threadIdx.x;
    const int base = blockIdx.x * 128;
    const float* __restrict__ agg = g_agg[br];

    for (int idx = tid; idx < 16384; idx += 256) {
        int r = idx >> 7, k = idx & 127;
        int node = base + r;
        As[idx] = (node < NN) ? agg[node * 128 + k] : 0.f;
        Wst[(idx & 127) * 130 + (idx >> 7)] = W[idx];   // W[k][j] -> Wst[j][k]
    }
    __syncthreads();

    const int tx = tid & 15;        // cols j = tx + 16*jj
    const int ty = tid >> 4;        // rows r = ty*8 + ii
    unsigned long long acc[8][8];
    #pragma unroll
    for (int ii = 0; ii < 8; ii++)
        #pragma unroll
        for (int jj = 0; jj < 8; jj++) acc[ii][jj] = 0ULL;

    const unsigned long long* Au = reinterpret_cast<const unsigned long long*>(As);
    #pragma unroll 4
    for (int kp = 0; kp < 64; kp++) {           // pairs (2k, 2k+1)
        unsigned long long a[8], b[8];
        #pragma unroll
        for (int ii = 0; ii < 8; ii++) a[ii] = Au[(ty * 8 + ii) * 64 + kp];
        #pragma unroll
        for (int jj = 0; jj < 8; jj++)
            b[jj] = *reinterpret_cast<const unsigned long long*>(&Wst[(tx + 16 * jj) * 130 + 2 * kp]);
        #pragma unroll
        for (int ii = 0; ii < 8; ii++)
            #pragma unroll
            for (int jj = 0; jj < 8; jj++)
                acc[ii][jj] = fma2(a[ii], b[jj], acc[ii][jj]);
    }

    float bv[8];
    #pragma unroll
    for (int jj = 0; jj < 8; jj++) bv[jj] = bias[tx + 16 * jj];
    float h[8][8];
    #pragma unroll
    for (int ii = 0; ii < 8; ii++)
        #pragma unroll
        for (int jj = 0; jj < 8; jj++) h[ii][jj] = sum2(acc[ii][jj]) + bv[jj];

    __syncthreads();   // all smem reads of As/Wst done; repurpose smem
    int*   gids = reinterpret_cast<int*>(sm);   // [128]
    float* invn = sm + 128;                      // [128]
    float* red  = sm + 16384;                    // [2048]

    for (int r = tid; r < 128; r += 256) {
        int node = base + r;
        gids[r] = (node < NN) ? gidv[node] : -1;
    }
    #pragma unroll
    for (int ii = 0; ii < 8; ii++) {
        float p = 0.f;
        #pragma unroll
        for (int jj = 0; jj < 8; jj++) p += h[ii][jj] * h[ii][jj];
        red[(ty * 8 + ii) * 16 + tx] = p;
    }
    __syncthreads();
    for (int r = tid; r < 128; r += 256) {
        float s = 0.f;
        #pragma unroll
        for (int t = 0; t < 16; t++) s += red[r * 16 + t];
        invn[r] = 1.f / fmaxf(sqrtf(s), 1e-12f);
    }
    __syncthreads();

    float sg[8][8];
    #pragma unroll
    for (int ii = 0; ii < 8; ii++) {
        float inv = invn[ty * 8 + ii];
        #pragma unroll
        for (int jj = 0; jj < 8; jj++) {
            float x = h[ii][jj] * inv;
            sg[ii][jj] = 1.f / (1.f + __expf(-x));   // relu(sigmoid) == sigmoid
        }
    }

    int lastValid = min(127, NN - 1 - base);
    int g0 = gids[0], gl = gids[lastValid];
    float* gsum = g_gsum[br];
    if (g0 == gl) {                       // all valid rows in one graph (common: gid sorted)
        #pragma unroll
        for (int jj = 0; jj < 8; jj++) {
            float q = 0.f;
            #pragma unroll
            for (int ii = 0; ii < 8; ii++) {
                int node = base + ty * 8 + ii;
                if (node < NN) q += sg[ii][jj];
            }
            red[(tx + 16 * jj) * 16 + ty] = q;
        }
        __syncthreads();
        for (int c = tid; c < 128; c += 256) {
            float s = 0.f;
            #pragma unroll
            for (int t = 0; t < 16; t++) s += red[c * 16 + t];
            atomicAdd(&gsum[g0 * 128 + c], s);
        }
    } else {                              // graph boundary inside block (rare)
        #pragma unroll
        for (int ii = 0; ii < 8; ii++) {
            int node = base + ty * 8 + ii;
            if (node < NN) {
                int g = gids[ty * 8 + ii];
                #pragma unroll
                for (int jj = 0; jj < 8; jj++)
                    atomicAdd(&gsum[g * 128 + tx + 16 * jj], sg[ii][jj]);
            }
        }
    }
}

__global__ void final_kernel(const float* __restrict__ Wc, const float* __restrict__ bc,
                             float* __restrict__ out) {
    __shared__ float h1[128], h2[128];
    __shared__ float rsum[2];
    int g = blockIdx.x, t = threadIdx.x;   // 64 threads
    float c1 = fmaxf((float)g_gcnt[0][g], 1.f);
    float c2 = fmaxf((float)g_gcnt[1][g], 1.f);
    for (int k = t; k < 128; k += 64) {
        h1[k] = g_gsum[0][g * 128 + k] / c1;
        h2[k] = g_gsum[1][g * 128 + k] / c2;
    }
    __syncthreads();
    float l1 = bc[t], l2 = bc[t];
    #pragma unroll 4
    for (int k = 0; k < 128; k++) {
        float w = Wc[k * 64 + t];
        l1 = fmaf(h1[k], w, l1);
        l2 = fmaf(h2[k], w, l2);
    }
    float d = l1 - l2 + 1e-6f;
    float sq = d * d;
    for (int o = 16; o > 0; o >>= 1) sq += __shfl_down_sync(0xffffffffu, sq, o);
    if ((t & 31) == 0) rsum[t >> 5] = sq;
    __syncthreads();
    if (t == 0) out[g] = sqrtf(rsum[0] + rsum[1]);
}

// ---------------- launch ----------------
extern "C" void kernel_launch(void* const* d_in, const int* in_sizes, int n_in,
                              void* d_out, int out_size) {
    const float* feat[2] = { (const float*)d_in[0], (const float*)d_in[1] };
    const int* src[2]    = { (const int*)d_in[2],   (const int*)d_in[5] };
    const int* dst[2]    = { (const int*)d_in[3],   (const int*)d_in[6] };
    const int* gid[2]    = { (const int*)d_in[4],   (const int*)d_in[7] };
    const float* W  = (const float*)d_in[8];
    const float* b  = (const float*)d_in[9];
    const float* Wc = (const float*)d_in[10];
    const float* bc = (const float*)d_in[11];
    float* out = (float*)d_out;

    const int SMEM_GEMM = (16384 + 130 * 128) * 4;   // 132096 B
    cudaFuncSetAttribute(gemm_epilogue_kernel,
                         cudaFuncAttributeMaxDynamicSharedMemorySize, SMEM_GEMM);

    const int EB = (NE + 255) / 256;     // 6250
    const int NB = (NN + 255) / 256;     // 391
    const int GB = (NN + 127) / 128;     // 782

    for (int br = 0; br < 2; br++) {
        zero_kernel<<<NB, 256>>>(br);
        degree_kernel<<<EB, 256>>>(src[br], dst[br], br);
        hist_kernel<<<128, 256>>>(gid[br], br);
        scan1_kernel<<<SCAN_BLOCKS, SCAN_BS>>>(br);
        scan2_kernel<<<1, 32>>>(br);
        scan3_kernel<<<SCAN_BLOCKS, SCAN_BS>>>(br);
        cursor_kernel<<<NB, 256>>>(br);
        scatter_kernel<<<EB, 256>>>(src[br], dst[br], br);
        agg_kernel<<<(NN * 32) / 256, 256>>>((const float4*)feat[br], br);
        gemm_epilogue_kernel<<<GB, 256, SMEM_GEMM>>>(br, W, b, gid[br]);
    }
    final_kernel<<<NG, 64>>>(Wc, bc, out);
}

// round 4
// speedup vs baseline: 1.1661x; 1.1661x over previous
#include <cuda_runtime.h>
#include <cuda_fp16.h>

#define NN 100000
#define NE 1600000
#define NG 128
#define NF 128
#define SCAN_BS 512
#define SCAN_BLOCKS ((NN + SCAN_BS - 1) / SCAN_BS)   // 196

// ---------------- scratch ----------------
__device__ int    g_deg_out[2][NN];
__device__ int    g_deg_in [2][NN];
__device__ int    g_off    [2][NN + 1];
__device__ int    g_cursor [2][NN + 1];
__device__ int    g_bsums  [2][256];
__device__ int    g_esrc   [2][NE];
__device__ __half g_P      [2][NN * NF];      // 25.6 MB each: (feat*c_out)@W in fp16
__device__ float  g_gsum   [2][NG * NF];
__device__ int    g_gcnt   [2][NG];

// ---------------- helpers ----------------
__device__ __forceinline__ unsigned long long fma2(unsigned long long a,
                                                   unsigned long long b,
                                                   unsigned long long c) {
    unsigned long long d;
    asm("fma.rn.f32x2 %0, %1, %2, %3;" : "=l"(d) : "l"(a), "l"(b), "l"(c));
    return d;
}
__device__ __forceinline__ float sum2(unsigned long long v) {
    float2 f = *reinterpret_cast<float2*>(&v);
    return f.x + f.y;
}

// ---------------- kernels (gridDim.y = branch) ----------------
__global__ void zero_kernel() {
    int br = blockIdx.y;
    int i = blockIdx.x * blockDim.x + threadIdx.x;
    if (i < NN) { g_deg_out[br][i] = 0; g_deg_in[br][i] = 0; }
    if (i < NG * NF) g_gsum[br][i] = 0.f;
    if (i < NG) g_gcnt[br][i] = 0;
}

__global__ void degree_kernel(const int* __restrict__ s1, const int* __restrict__ d1,
                              const int* __restrict__ s2, const int* __restrict__ d2) {
    int br = blockIdx.y;
    const int* s = br ? s2 : s1;
    const int* d = br ? d2 : d1;
    int i = blockIdx.x * blockDim.x + threadIdx.x;
    if (i < NE) {
        atomicAdd(&g_deg_out[br][s[i]], 1);
        atomicAdd(&g_deg_in [br][d[i]], 1);
    }
}

__global__ void hist_kernel(const int* __restrict__ g1, const int* __restrict__ g2) {
    int br = blockIdx.y;
    const int* gid = br ? g2 : g1;
    __shared__ int sh[NG];
    int tid = threadIdx.x;
    if (tid < NG) sh[tid] = 0;
    __syncthreads();
    for (int i = blockIdx.x * blockDim.x + tid; i < NN; i += gridDim.x * blockDim.x)
        atomicAdd(&sh[gid[i]], 1);
    __syncthreads();
    if (tid < NG && sh[tid]) atomicAdd(&g_gcnt[br][tid], sh[tid]);
}

__global__ void scan1_kernel() {
    int br = blockIdx.y;
    __shared__ int sh[SCAN_BS];
    int tid = threadIdx.x;
    int i = blockIdx.x * SCAN_BS + tid;
    int v = (i < NN) ? g_deg_in[br][i] : 0;
    sh[tid] = v;
    __syncthreads();
    for (int o = 1; o < SCAN_BS; o <<= 1) {
        int t = (tid >= o) ? sh[tid - o] : 0;
        __syncthreads();
        sh[tid] += t;
        __syncthreads();
    }
    if (i < NN) g_off[br][i + 1] = sh[tid];
    if (tid == SCAN_BS - 1) g_bsums[br][blockIdx.x] = sh[tid];
}

__global__ void scan2_kernel() {           // parallel block scan over 196 block sums
    int br = blockIdx.y;
    __shared__ int sh[256];
    int tid = threadIdx.x;
    int v = (tid < SCAN_BLOCKS) ? g_bsums[br][tid] : 0;
    sh[tid] = v;
    __syncthreads();
    for (int o = 1; o < 256; o <<= 1) {
        int t = (tid >= o) ? sh[tid - o] : 0;
        __syncthreads();
        sh[tid] += t;
        __syncthreads();
    }
    if (tid < SCAN_BLOCKS) g_bsums[br][tid] = sh[tid] - v;   // exclusive
}

__global__ void scan3_kernel() {
    int br = blockIdx.y;
    int i = blockIdx.x * SCAN_BS + threadIdx.x;
    if (i < NN) {
        int v = g_off[br][i + 1] + g_bsums[br][i >> 9];
        g_off[br][i + 1] = v;
        g_cursor[br][i + 1] = v;
    }
    if (i == 0) { g_off[br][0] = 0; g_cursor[br][0] = 0; }
}

__global__ void scatter_kernel(const int* __restrict__ s1, const int* __restrict__ d1,
                               const int* __restrict__ s2, const int* __restrict__ d2) {
    int br = blockIdx.y;
    const int* s = br ? s2 : s1;
    const int* d = br ? d2 : d1;
    int i = blockIdx.x * blockDim.x + threadIdx.x;
    if (i < NE) {
        int p = atomicAdd(&g_cursor[br][d[i]], 1);
        g_esrc[br][p] = s[i];
    }
}

// P = (feat * deg_out^-1/2) @ W  -> fp16.  Block = 128 nodes x 128 cols.
__global__ __launch_bounds__(256, 1) void gemm_scale_kernel(
        const float* __restrict__ f1, const float* __restrict__ f2,
        const float* __restrict__ W) {
    extern __shared__ float sm[];
    float* As  = sm;                 // [128][128]
    float* Wst = sm + 16384;         // [128 j][130] (W transposed, k-contiguous)
    float* cs  = sm + 16384 + 16640; // [128] row scales
    int br = blockIdx.y;
    const float* feat = br ? f2 : f1;
    const int tid = threadIdx.x;
    const int base = blockIdx.x * 128;

    for (int r = tid; r < 128; r += 256) {
        int node = base + r;
        cs[r] = (node < NN) ? rsqrtf(fmaxf((float)g_deg_out[br][node], 1.f)) : 0.f;
    }
    __syncthreads();
    for (int idx = tid; idx < 16384; idx += 256) {
        int r = idx >> 7, k = idx & 127;
        int node = base + r;
        As[idx] = (node < NN) ? feat[node * 128 + k] * cs[r] : 0.f;
        Wst[k * 130 + r] = W[idx];   // here r plays the role of j (idx = k*128 + j)? no:
        // W row-major [k][j]: idx>>7 = k_w, idx&127 = j_w
    }
    __syncthreads();
    // NOTE: the Wst line above used (idx>>7, idx&127) roles swapped via variable reuse:
    // Wst[(idx&127)*130 + (idx>>7)] is the intent; rewritten correctly below is not possible
    // after sync, so we instead wrote Wst[k*130 + r] with r=idx>>7, k=idx&127 which equals
    // Wst[(idx&127)*130 + (idx>>7)].  (j := idx&127 stored per-row, k-contiguous.)

    const int tx = tid & 15;   // cols j = tx + 16*jj
    const int ty = tid >> 4;   // rows r = ty*8 + ii
    unsigned long long acc[8][8];
    #pragma unroll
    for (int ii = 0; ii < 8; ii++)
        #pragma unroll
        for (int jj = 0; jj < 8; jj++) acc[ii][jj] = 0ULL;

    const unsigned long long* Au = reinterpret_cast<const unsigned long long*>(As);
    #pragma unroll 4
    for (int kp = 0; kp < 64; kp++) {
        unsigned long long a[8], b[8];
        #pragma unroll
        for (int ii = 0; ii < 8; ii++) a[ii] = Au[(ty * 8 + ii) * 64 + kp];
        #pragma unroll
        for (int jj = 0; jj < 8; jj++)
            b[jj] = *reinterpret_cast<const unsigned long long*>(&Wst[(tx + 16 * jj) * 130 + 2 * kp]);
        #pragma unroll
        for (int ii = 0; ii < 8; ii++)
            #pragma unroll
            for (int jj = 0; jj < 8; jj++)
                acc[ii][jj] = fma2(a[ii], b[jj], acc[ii][jj]);
    }

    __syncthreads();                     // done reading As/Wst; stage fp16 output in smem
    __half* sh = reinterpret_cast<__half*>(sm);   // [128][128] halves (32 KB)
    #pragma unroll
    for (int ii = 0; ii < 8; ii++)
        #pragma unroll
        for (int jj = 0; jj < 8; jj++)
            sh[(ty * 8 + ii) * 128 + tx + 16 * jj] = __float2half_rn(sum2(acc[ii][jj]));
    __syncthreads();

    const uint4* smu = reinterpret_cast<const uint4*>(sm);
    uint4* Pu = reinterpret_cast<uint4*>(g_P[br]);
    for (int e = tid; e < 2048; e += 256) {        // 2048 * 16B = 32 KB
        int node = base + (e >> 4);
        if (node < NN) Pu[base * 16 + e] = smu[e];
    }
}

// Gather P by CSR + full epilogue: *deg_in^-1/2 + b, L2 norm, sigmoid, graph sums.
// Warp per node; per-warp smem graph accumulator flushed on gid change (gid sorted).
__global__ __launch_bounds__(256) void agg_epilogue_kernel(
        const int* __restrict__ g1, const int* __restrict__ g2,
        const float* __restrict__ bias) {
    __shared__ float sacc[8][128];
    int br = blockIdx.y;
    const int* gid = br ? g2 : g1;
    const int w = threadIdx.x >> 5, lane = threadIdx.x & 31;
    const int* __restrict__ off  = g_off[br];
    const int* __restrict__ esrc = g_esrc[br];
    const uint2* __restrict__ Pu = reinterpret_cast<const uint2*>(g_P[br]);
    float* gsum = g_gsum[br];
    const float4 bv = reinterpret_cast<const float4*>(bias)[lane];

    reinterpret_cast<float4*>(sacc[w])[lane] = make_float4(0.f, 0.f, 0.f, 0.f);
    int curg = -1;
    const int baseN = blockIdx.x * 256;

    for (int t = 0; t < 32; t++) {
        int node = baseN + t * 8 + w;
        if (node >= NN) break;                       // monotonic in t
        int g = gid[node];
        if (g != curg) {
            if (curg >= 0) {
                float4 s = reinterpret_cast<float4*>(sacc[w])[lane];
                atomicAdd(&gsum[curg * 128 + lane * 4 + 0], s.x);
                atomicAdd(&gsum[curg * 128 + lane * 4 + 1], s.y);
                atomicAdd(&gsum[curg * 128 + lane * 4 + 2], s.z);
                atomicAdd(&gsum[curg * 128 + lane * 4 + 3], s.w);
                reinterpret_cast<float4*>(sacc[w])[lane] = make_float4(0.f, 0.f, 0.f, 0.f);
            }
            curg = g;
        }
        int beg = off[node], end = off[node + 1];
        float ax = 0.f, ay = 0.f, az = 0.f, aw = 0.f;
        int e = beg;
        while (e < end) {
            int cnt = min(32, end - e);
            int sid = (lane < cnt) ? esrc[e + lane] : 0;   // all-lane edge-id fetch
            int j = 0;
            for (; j + 4 <= cnt; j += 4) {
                int s0 = __shfl_sync(0xffffffffu, sid, j + 0);
                int s1 = __shfl_sync(0xffffffffu, sid, j + 1);
                int s2 = __shfl_sync(0xffffffffu, sid, j + 2);
                int s3 = __shfl_sync(0xffffffffu, sid, j + 3);
                uint2 v0 = Pu[s0 * 32 + lane];
                uint2 v1 = Pu[s1 * 32 + lane];
                uint2 v2 = Pu[s2 * 32 + lane];
                uint2 v3 = Pu[s3 * 32 + lane];
                #define ACC_V(v) { \
                    const __half2* hp = reinterpret_cast<const __half2*>(&(v)); \
                    float2 fa = __half22float2(hp[0]); \
                    float2 fb = __half22float2(hp[1]); \
                    ax += fa.x; ay += fa.y; az += fb.x; aw += fb.y; }
                ACC_V(v0) ACC_V(v1) ACC_V(v2) ACC_V(v3)
            }
            for (; j < cnt; j++) {
                int s0 = __shfl_sync(0xffffffffu, sid, j);
                uint2 v0 = Pu[s0 * 32 + lane];
                ACC_V(v0)
                #undef ACC_V
            }
            e += cnt;
        }
        float cin = rsqrtf(fmaxf((float)(end - beg), 1.f));
        float hx = ax * cin + bv.x;
        float hy = ay * cin + bv.y;
        float hz = az * cin + bv.z;
        float hw = aw * cin + bv.w;
        float p = hx * hx + hy * hy + hz * hz + hw * hw;
        #pragma unroll
        for (int o = 16; o > 0; o >>= 1) p += __shfl_xor_sync(0xffffffffu, p, o);
        float inv = 1.f / fmaxf(sqrtf(p), 1e-12f);
        float sx = 1.f / (1.f + __expf(-hx * inv));   // relu(sigmoid)==sigmoid
        float sy = 1.f / (1.f + __expf(-hy * inv));
        float sz = 1.f / (1.f + __expf(-hz * inv));
        float sw = 1.f / (1.f + __expf(-hw * inv));
        float4 s = reinterpret_cast<float4*>(sacc[w])[lane];
        s.x += sx; s.y += sy; s.z += sz; s.w += sw;
        reinterpret_cast<float4*>(sacc[w])[lane] = s;
    }
    if (curg >= 0) {
        float4 s = reinterpret_cast<float4*>(sacc[w])[lane];
        atomicAdd(&gsum[curg * 128 + lane * 4 + 0], s.x);
        atomicAdd(&gsum[curg * 128 + lane * 4 + 1], s.y);
        atomicAdd(&gsum[curg * 128 + lane * 4 + 2], s.z);
        atomicAdd(&gsum[curg * 128 + lane * 4 + 3], s.w);
    }
}

__global__ void final_kernel(const float* __restrict__ Wc, const float* __restrict__ bc,
                             float* __restrict__ out) {
    __shared__ float h1[128], h2[128];
    __shared__ float rsum[2];
    int g = blockIdx.x, t = threadIdx.x;   // 64 threads
    float c1 = fmaxf((float)g_gcnt[0][g], 1.f);
    float c2 = fmaxf((float)g_gcnt[1][g], 1.f);
    for (int k = t; k < 128; k += 64) {
        h1[k] = g_gsum[0][g * 128 + k] / c1;
        h2[k] = g_gsum[1][g * 128 + k] / c2;
    }
    __syncthreads();
    float l1 = bc[t], l2 = bc[t];
    #pragma unroll 4
    for (int k = 0; k < 128; k++) {
        float w = Wc[k * 64 + t];
        l1 = fmaf(h1[k], w, l1);
        l2 = fmaf(h2[k], w, l2);
    }
    float d = l1 - l2 + 1e-6f;
    float sq = d * d;
    for (int o = 16; o > 0; o >>= 1) sq += __shfl_down_sync(0xffffffffu, sq, o);
    if ((t & 31) == 0) rsum[t >> 5] = sq;
    __syncthreads();
    if (t == 0) out[g] = sqrtf(rsum[0] + rsum[1]);
}

// ---------------- launch ----------------
extern "C" void kernel_launch(void* const* d_in, const int* in_sizes, int n_in,
                              void* d_out, int out_size) {
    const float* feat1 = (const float*)d_in[0];
    const float* feat2 = (const float*)d_in[1];
    const int* src1 = (const int*)d_in[2];
    const int* dst1 = (const int*)d_in[3];
    const int* gid1 = (const int*)d_in[4];
    const int* src2 = (const int*)d_in[5];
    const int* dst2 = (const int*)d_in[6];
    const int* gid2 = (const int*)d_in[7];
    const float* W  = (const float*)d_in[8];
    const float* b  = (const float*)d_in[9];
    const float* Wc = (const float*)d_in[10];
    const float* bc = (const float*)d_in[11];
    float* out = (float*)d_out;

    const int SMEM_GEMM = (16384 + 130 * 128 + 128) * 4;   // 132608 B
    cudaFuncSetAttribute(gemm_scale_kernel,
                         cudaFuncAttributeMaxDynamicSharedMemorySize, SMEM_GEMM);

    const int EB = (NE + 255) / 256;     // 6250
    const int NB = (NN + 255) / 256;     // 391
    const int GB = (NN + 127) / 128;     // 782

    zero_kernel   <<<dim3(NB, 2), 256>>>();
    degree_kernel <<<dim3(EB, 2), 256>>>(src1, dst1, src2, dst2);
    hist_kernel   <<<dim3(128, 2), 256>>>(gid1, gid2);
    scan1_kernel  <<<dim3(SCAN_BLOCKS, 2), SCAN_BS>>>();
    scan2_kernel  <<<dim3(1, 2), 256>>>();
    scan3_kernel  <<<dim3(SCAN_BLOCKS, 2), SCAN_BS>>>();
    scatter_kernel<<<dim3(EB, 2), 256>>>(src1, dst1, src2, dst2);
    gemm_scale_kernel<<<dim3(GB, 2), 256, SMEM_GEMM>>>(feat1, feat2, W);
    agg_epilogue_kernel<<<dim3(NB, 2), 256>>>(gid1, gid2, b);
    final_kernel  <<<NG, 64>>>(Wc, bc, out);
}

// round 5
// speedup vs baseline: 1.9420x; 1.6655x over previous
#include <cuda_runtime.h>
#include <cuda_fp16.h>

#define NN 100000
#define NE 1600000
#define NG 128
#define NF 128
#define SCAN_BS 512
#define SCAN_BLOCKS ((NN + SCAN_BS - 1) / SCAN_BS)   // 196
#define WST 136                                       // padded k-stride for Ws (halves)

// ---------------- scratch ----------------
__device__ int    g_deg_out[2][NN];
__device__ int    g_deg_in [2][NN];
__device__ int    g_off    [2][NN + 1];
__device__ int    g_cursor [2][NN + 1];
__device__ int    g_bsums  [2][256];
__device__ int    g_esrc   [2][NE];
__device__ __half g_P      [2][NN * NF];      // 25.6 MB each: (feat*c_out)@W in fp16
__device__ __half g_Wh     [NF * WST];        // W transposed (n-major, k-contig, padded)
__device__ float  g_gsum   [2][NG * NF];
__device__ int    g_gcnt   [2][NG];

// ---------------- kernels (gridDim.y = branch) ----------------
__global__ void zero_kernel() {
    int br = blockIdx.y;
    int i = blockIdx.x * blockDim.x + threadIdx.x;
    if (i < NN) { g_deg_out[br][i] = 0; g_deg_in[br][i] = 0; }
    if (i < NG * NF) g_gsum[br][i] = 0.f;
    if (i < NG) g_gcnt[br][i] = 0;
}

__global__ void wconv_kernel(const float* __restrict__ W) {
    int i = blockIdx.x * 256 + threadIdx.x;
    if (i < NF * NF) {
        int k = i >> 7, n = i & 127;
        g_Wh[n * WST + k] = __float2half_rn(W[i]);
    }
}

__global__ void degree_kernel(const int* __restrict__ s1, const int* __restrict__ d1,
                              const int* __restrict__ s2, const int* __restrict__ d2) {
    int br = blockIdx.y;
    const int* s = br ? s2 : s1;
    const int* d = br ? d2 : d1;
    int i = blockIdx.x * blockDim.x + threadIdx.x;
    if (i < NE) {
        atomicAdd(&g_deg_out[br][s[i]], 1);
        atomicAdd(&g_deg_in [br][d[i]], 1);
    }
}

__global__ void hist_kernel(const int* __restrict__ g1, const int* __restrict__ g2) {
    int br = blockIdx.y;
    const int* gid = br ? g2 : g1;
    __shared__ int sh[NG];
    int tid = threadIdx.x;
    if (tid < NG) sh[tid] = 0;
    __syncthreads();
    for (int i = blockIdx.x * blockDim.x + tid; i < NN; i += gridDim.x * blockDim.x)
        atomicAdd(&sh[gid[i]], 1);
    __syncthreads();
    if (tid < NG && sh[tid]) atomicAdd(&g_gcnt[br][tid], sh[tid]);
}

__global__ void scan1_kernel() {
    int br = blockIdx.y;
    __shared__ int sh[SCAN_BS];
    int tid = threadIdx.x;
    int i = blockIdx.x * SCAN_BS + tid;
    int v = (i < NN) ? g_deg_in[br][i] : 0;
    sh[tid] = v;
    __syncthreads();
    for (int o = 1; o < SCAN_BS; o <<= 1) {
        int t = (tid >= o) ? sh[tid - o] : 0;
        __syncthreads();
        sh[tid] += t;
        __syncthreads();
    }
    if (i < NN) g_off[br][i + 1] = sh[tid];
    if (tid == SCAN_BS - 1) g_bsums[br][blockIdx.x] = sh[tid];
}

__global__ void scan2_kernel() {
    int br = blockIdx.y;
    __shared__ int sh[256];
    int tid = threadIdx.x;
    int v = (tid < SCAN_BLOCKS) ? g_bsums[br][tid] : 0;
    sh[tid] = v;
    __syncthreads();
    for (int o = 1; o < 256; o <<= 1) {
        int t = (tid >= o) ? sh[tid - o] : 0;
        __syncthreads();
        sh[tid] += t;
        __syncthreads();
    }
    if (tid < SCAN_BLOCKS) g_bsums[br][tid] = sh[tid] - v;   // exclusive
}

__global__ void scan3_kernel() {
    int br = blockIdx.y;
    int i = blockIdx.x * SCAN_BS + threadIdx.x;
    if (i < NN) {
        int v = g_off[br][i + 1] + g_bsums[br][i >> 9];
        g_off[br][i + 1] = v;
        g_cursor[br][i + 1] = v;
    }
    if (i == 0) { g_off[br][0] = 0; g_cursor[br][0] = 0; }
}

__global__ void scatter_kernel(const int* __restrict__ s1, const int* __restrict__ d1,
                               const int* __restrict__ s2, const int* __restrict__ d2) {
    int br = blockIdx.y;
    const int* s = br ? s2 : s1;
    const int* d = br ? d2 : d1;
    int i = blockIdx.x * blockDim.x + threadIdx.x;
    if (i < NE) {
        int p = atomicAdd(&g_cursor[br][d[i]], 1);
        g_esrc[br][p] = s[i];
    }
}

// ---------------- tensor-core GEMM: P = (feat * deg_out^-1/2) @ W -> fp16 ----------------
// Block = 128 rows x 128 cols, 8 warps (16 rows each). HMMA m16n8k16 fp16->fp32.
__device__ __forceinline__ unsigned h2u(__half2 h) { return *reinterpret_cast<unsigned*>(&h); }

__global__ __launch_bounds__(256) void gemm_mma_kernel(
        const float* __restrict__ f1, const float* __restrict__ f2) {
    extern __shared__ __half Ws[];    // [128 n][WST k]
    int br = blockIdx.y;
    const float* __restrict__ feat = br ? f2 : f1;
    const int tid = threadIdx.x;

    {   // copy pre-transposed fp16 W into smem (vectorized, no conversion)
        const uint4* s = reinterpret_cast<const uint4*>(g_Wh);
        uint4* dsm = reinterpret_cast<uint4*>(Ws);
        #pragma unroll
        for (int i = tid; i < NF * WST * 2 / 16; i += 256) dsm[i] = s[i];
    }
    __syncthreads();

    const int w = tid >> 5, lane = tid & 31;
    const int g = lane >> 2, tg = lane & 3;
    const int base = blockIdx.x * 128;
    const int row0 = base + w * 16 + g;
    const int row1 = row0 + 8;
    const bool v0 = row0 < NN, v1 = row1 < NN;
    const float c0 = v0 ? rsqrtf(fmaxf((float)g_deg_out[br][row0], 1.f)) : 0.f;
    const float c1 = v1 ? rsqrtf(fmaxf((float)g_deg_out[br][row1], 1.f)) : 0.f;

    // preload A fragments for all 8 k-chunks (scale folded into fp32->fp16 convert)
    unsigned a[8][4];
    const float2 z2 = make_float2(0.f, 0.f);
    #pragma unroll
    for (int kc = 0; kc < 8; kc++) {
        int k0 = kc * 16 + tg * 2;
        float2 x0 = v0 ? *reinterpret_cast<const float2*>(&feat[row0 * 128 + k0])     : z2;
        float2 x1 = v1 ? *reinterpret_cast<const float2*>(&feat[row1 * 128 + k0])     : z2;
        float2 x2 = v0 ? *reinterpret_cast<const float2*>(&feat[row0 * 128 + k0 + 8]) : z2;
        float2 x3 = v1 ? *reinterpret_cast<const float2*>(&feat[row1 * 128 + k0 + 8]) : z2;
        a[kc][0] = h2u(__floats2half2_rn(x0.x * c0, x0.y * c0));
        a[kc][1] = h2u(__floats2half2_rn(x1.x * c1, x1.y * c1));
        a[kc][2] = h2u(__floats2half2_rn(x2.x * c0, x2.y * c0));
        a[kc][3] = h2u(__floats2half2_rn(x3.x * c1, x3.y * c1));
    }

    __half* __restrict__ P = g_P[br];
    #pragma unroll
    for (int nt = 0; nt < 16; nt++) {
        float d0 = 0.f, d1 = 0.f, d2 = 0.f, d3 = 0.f;
        const __half* wrow = &Ws[(nt * 8 + g) * WST + tg * 2];
        #pragma unroll
        for (int kc = 0; kc < 8; kc++) {
            unsigned b0 = *reinterpret_cast<const unsigned*>(wrow + kc * 16);
            unsigned b1 = *reinterpret_cast<const unsigned*>(wrow + kc * 16 + 8);
            asm volatile(
                "mma.sync.aligned.m16n8k16.row.col.f32.f16.f16.f32 "
                "{%0,%1,%2,%3}, {%4,%5,%6,%7}, {%8,%9}, {%0,%1,%2,%3};"
                : "+f"(d0), "+f"(d1), "+f"(d2), "+f"(d3)
                : "r"(a[kc][0]), "r"(a[kc][1]), "r"(a[kc][2]), "r"(a[kc][3]),
                  "r"(b0), "r"(b1));
        }
        int col = nt * 8 + tg * 2;
        if (v0) *reinterpret_cast<__half2*>(&P[row0 * 128 + col]) = __floats2half2_rn(d0, d1);
        if (v1) *reinterpret_cast<__half2*>(&P[row1 * 128 + col]) = __floats2half2_rn(d2, d3);
    }
}

// ---------------- gather + epilogue (unchanged from R4, passing) ----------------
__global__ __launch_bounds__(256) void agg_epilogue_kernel(
        const int* __restrict__ g1, const int* __restrict__ g2,
        const float* __restrict__ bias) {
    __shared__ float sacc[8][128];
    int br = blockIdx.y;
    const int* gid = br ? g2 : g1;
    const int w = threadIdx.x >> 5, lane = threadIdx.x & 31;
    const int* __restrict__ off  = g_off[br];
    const int* __restrict__ esrc = g_esrc[br];
    const uint2* __restrict__ Pu = reinterpret_cast<const uint2*>(g_P[br]);
    float* gsum = g_gsum[br];
    const float4 bv = reinterpret_cast<const float4*>(bias)[lane];

    reinterpret_cast<float4*>(sacc[w])[lane] = make_float4(0.f, 0.f, 0.f, 0.f);
    int curg = -1;
    const int baseN = blockIdx.x * 256;

    for (int t = 0; t < 32; t++) {
        int node = baseN + t * 8 + w;
        if (node >= NN) break;
        int g = gid[node];
        if (g != curg) {
            if (curg >= 0) {
                float4 s = reinterpret_cast<float4*>(sacc[w])[lane];
                atomicAdd(&gsum[curg * 128 + lane * 4 + 0], s.x);
                atomicAdd(&gsum[curg * 128 + lane * 4 + 1], s.y);
                atomicAdd(&gsum[curg * 128 + lane * 4 + 2], s.z);
                atomicAdd(&gsum[curg * 128 + lane * 4 + 3], s.w);
                reinterpret_cast<float4*>(sacc[w])[lane] = make_float4(0.f, 0.f, 0.f, 0.f);
            }
            curg = g;
        }
        int beg = off[node], end = off[node + 1];
        float ax = 0.f, ay = 0.f, az = 0.f, aw = 0.f;
        int e = beg;
        while (e < end) {
            int cnt = min(32, end - e);
            int sid = (lane < cnt) ? esrc[e + lane] : 0;
            int j = 0;
            for (; j + 4 <= cnt; j += 4) {
                int s0 = __shfl_sync(0xffffffffu, sid, j + 0);
                int s1 = __shfl_sync(0xffffffffu, sid, j + 1);
                int s2 = __shfl_sync(0xffffffffu, sid, j + 2);
                int s3 = __shfl_sync(0xffffffffu, sid, j + 3);
                uint2 v0 = Pu[s0 * 32 + lane];
                uint2 v1 = Pu[s1 * 32 + lane];
                uint2 v2 = Pu[s2 * 32 + lane];
                uint2 v3 = Pu[s3 * 32 + lane];
                #define ACC_V(v) { \
                    const __half2* hp = reinterpret_cast<const __half2*>(&(v)); \
                    float2 fa = __half22float2(hp[0]); \
                    float2 fb = __half22float2(hp[1]); \
                    ax += fa.x; ay += fa.y; az += fb.x; aw += fb.y; }
                ACC_V(v0) ACC_V(v1) ACC_V(v2) ACC_V(v3)
            }
            for (; j < cnt; j++) {
                int s0 = __shfl_sync(0xffffffffu, sid, j);
                uint2 v0 = Pu[s0 * 32 + lane];
                ACC_V(v0)
                #undef ACC_V
            }
            e += cnt;
        }
        float cin = rsqrtf(fmaxf((float)(end - beg), 1.f));
        float hx = ax * cin + bv.x;
        float hy = ay * cin + bv.y;
        float hz = az * cin + bv.z;
        float hw = aw * cin + bv.w;
        float p = hx * hx + hy * hy + hz * hz + hw * hw;
        #pragma unroll
        for (int o = 16; o > 0; o >>= 1) p += __shfl_xor_sync(0xffffffffu, p, o);
        float inv = 1.f / fmaxf(sqrtf(p), 1e-12f);
        float sx = 1.f / (1.f + __expf(-hx * inv));
        float sy = 1.f / (1.f + __expf(-hy * inv));
        float sz = 1.f / (1.f + __expf(-hz * inv));
        float sw = 1.f / (1.f + __expf(-hw * inv));
        float4 s = reinterpret_cast<float4*>(sacc[w])[lane];
        s.x += sx; s.y += sy; s.z += sz; s.w += sw;
        reinterpret_cast<float4*>(sacc[w])[lane] = s;
    }
    if (curg >= 0) {
        float4 s = reinterpret_cast<float4*>(sacc[w])[lane];
        atomicAdd(&gsum[curg * 128 + lane * 4 + 0], s.x);
        atomicAdd(&gsum[curg * 128 + lane * 4 + 1], s.y);
        atomicAdd(&gsum[curg * 128 + lane * 4 + 2], s.z);
        atomicAdd(&gsum[curg * 128 + lane * 4 + 3], s.w);
    }
}

__global__ void final_kernel(const float* __restrict__ Wc, const float* __restrict__ bc,
                             float* __restrict__ out) {
    __shared__ float h1[128], h2[128];
    __shared__ float rsum[2];
    int g = blockIdx.x, t = threadIdx.x;   // 64 threads
    float c1 = fmaxf((float)g_gcnt[0][g], 1.f);
    float c2 = fmaxf((float)g_gcnt[1][g], 1.f);
    for (int k = t; k < 128; k += 64) {
        h1[k] = g_gsum[0][g * 128 + k] / c1;
        h2[k] = g_gsum[1][g * 128 + k] / c2;
    }
    __syncthreads();
    float l1 = bc[t], l2 = bc[t];
    #pragma unroll 4
    for (int k = 0; k < 128; k++) {
        float w = Wc[k * 64 + t];
        l1 = fmaf(h1[k], w, l1);
        l2 = fmaf(h2[k], w, l2);
    }
    float d = l1 - l2 + 1e-6f;
    float sq = d * d;
    for (int o = 16; o > 0; o >>= 1) sq += __shfl_down_sync(0xffffffffu, sq, o);
    if ((t & 31) == 0) rsum[t >> 5] = sq;
    __syncthreads();
    if (t == 0) out[g] = sqrtf(rsum[0] + rsum[1]);
}

// ---------------- launch ----------------
extern "C" void kernel_launch(void* const* d_in, const int* in_sizes, int n_in,
                              void* d_out, int out_size) {
    const float* feat1 = (const float*)d_in[0];
    const float* feat2 = (const float*)d_in[1];
    const int* src1 = (const int*)d_in[2];
    const int* dst1 = (const int*)d_in[3];
    const int* gid1 = (const int*)d_in[4];
    const int* src2 = (const int*)d_in[5];
    const int* dst2 = (const int*)d_in[6];
    const int* gid2 = (const int*)d_in[7];
    const float* W  = (const float*)d_in[8];
    const float* b  = (const float*)d_in[9];
    const float* Wc = (const float*)d_in[10];
    const float* bc = (const float*)d_in[11];
    float* out = (float*)d_out;

    const int EB = (NE + 255) / 256;     // 6250
    const int NB = (NN + 255) / 256;     // 391
    const int GB = (NN + 127) / 128;     // 782
    const int SMEM_MMA = NF * WST * 2;   // 34816 B

    zero_kernel   <<<dim3(NB, 2), 256>>>();
    wconv_kernel  <<<64, 256>>>(W);
    degree_kernel <<<dim3(EB, 2), 256>>>(src1, dst1, src2, dst2);
    hist_kernel   <<<dim3(128, 2), 256>>>(gid1, gid2);
    scan1_kernel  <<<dim3(SCAN_BLOCKS, 2), SCAN_BS>>>();
    scan2_kernel  <<<dim3(1, 2), 256>>>();
    scan3_kernel  <<<dim3(SCAN_BLOCKS, 2), SCAN_BS>>>();
    scatter_kernel<<<dim3(EB, 2), 256>>>(src1, dst1, src2, dst2);
    gemm_mma_kernel<<<dim3(GB, 2), 256, SMEM_MMA>>>(feat1, feat2);
    agg_epilogue_kernel<<<dim3(NB, 2), 256>>>(gid1, gid2, b);
    final_kernel  <<<NG, 64>>>(Wc, bc, out);
}

// round 6
// speedup vs baseline: 2.0610x; 1.0613x over previous
#include <cuda_runtime.h>
#include <cuda_fp16.h>

#define NN 100000
#define NE 1600000
#define NG 128
#define NF 128
#define SCAN_BS 512
#define SCAN_BLOCKS ((NN + SCAN_BS - 1) / SCAN_BS)   // 196
#define WST 136                                       // padded k-stride for Ws (halves)

// ---------------- scratch ----------------
__device__ int    g_deg_out[2][NN];
__device__ int    g_deg_in [2][NN];
__device__ int    g_off    [2][NN + 1];
__device__ int    g_cursor [2][NN + 1];
__device__ int    g_bsums  [2][256];
__device__ int    g_esrc   [2][NE];
__device__ __half g_P      [2][NN * NF];      // 25.6 MB each: (feat*c_out)@W in fp16
__device__ __half g_Wh     [NF * WST];        // W transposed (n-major, k-contig, padded)
__device__ float  g_gsum   [2][NG * NF];
__device__ int    g_gcnt   [2][NG];

// ---------------- kernels (gridDim.y = branch) ----------------
// zero scratch + convert W to transposed fp16 (branch 0 blocks only)
__global__ void zw_kernel(const float* __restrict__ W) {
    int br = blockIdx.y;
    int i = blockIdx.x * blockDim.x + threadIdx.x;
    if (i < NN) { g_deg_out[br][i] = 0; g_deg_in[br][i] = 0; }
    if (i < NG * NF) g_gsum[br][i] = 0.f;
    if (i < NG) g_gcnt[br][i] = 0;
    if (br == 0 && i < NF * NF) {
        int k = i >> 7, n = i & 127;
        g_Wh[n * WST + k] = __float2half_rn(W[i]);
    }
}

__global__ void degree_kernel(const int* __restrict__ s1, const int* __restrict__ d1,
                              const int* __restrict__ s2, const int* __restrict__ d2) {
    int br = blockIdx.y;
    const int* s = br ? s2 : s1;
    const int* d = br ? d2 : d1;
    int i = blockIdx.x * blockDim.x + threadIdx.x;
    if (i < NE) {
        atomicAdd(&g_deg_out[br][s[i]], 1);
        atomicAdd(&g_deg_in [br][d[i]], 1);
    }
}

__global__ void scan1_kernel() {
    int br = blockIdx.y;
    __shared__ int sh[SCAN_BS];
    int tid = threadIdx.x;
    int i = blockIdx.x * SCAN_BS + tid;
    int v = (i < NN) ? g_deg_in[br][i] : 0;
    sh[tid] = v;
    __syncthreads();
    for (int o = 1; o < SCAN_BS; o <<= 1) {
        int t = (tid >= o) ? sh[tid - o] : 0;
        __syncthreads();
        sh[tid] += t;
        __syncthreads();
    }
    if (i < NN) g_off[br][i + 1] = sh[tid];
    if (tid == SCAN_BS - 1) g_bsums[br][blockIdx.x] = sh[tid];
}

__global__ void scan2_kernel() {
    int br = blockIdx.y;
    __shared__ int sh[256];
    int tid = threadIdx.x;
    int v = (tid < SCAN_BLOCKS) ? g_bsums[br][tid] : 0;
    sh[tid] = v;
    __syncthreads();
    for (int o = 1; o < 256; o <<= 1) {
        int t = (tid >= o) ? sh[tid - o] : 0;
        __syncthreads();
        sh[tid] += t;
        __syncthreads();
    }
    if (tid < SCAN_BLOCKS) g_bsums[br][tid] = sh[tid] - v;   // exclusive
}

__global__ void scan3_kernel() {
    int br = blockIdx.y;
    int i = blockIdx.x * SCAN_BS + threadIdx.x;
    if (i < NN) {
        int v = g_off[br][i + 1] + g_bsums[br][i >> 9];
        g_off[br][i + 1] = v;
        g_cursor[br][i + 1] = v;
    }
    if (i == 0) { g_off[br][0] = 0; g_cursor[br][0] = 0; }
}

__global__ void scatter_kernel(const int* __restrict__ s1, const int* __restrict__ d1,
                               const int* __restrict__ s2, const int* __restrict__ d2) {
    int br = blockIdx.y;
    const int* s = br ? s2 : s1;
    const int* d = br ? d2 : d1;
    int i = blockIdx.x * blockDim.x + threadIdx.x;
    if (i < NE) {
        int p = atomicAdd(&g_cursor[br][d[i]], 1);
        g_esrc[br][p] = s[i];
    }
}

// ---------------- tensor-core GEMM: P = (feat * deg_out^-1/2) @ W -> fp16 ----------------
__device__ __forceinline__ unsigned h2u(__half2 h) { return *reinterpret_cast<unsigned*>(&h); }

__global__ __launch_bounds__(256) void gemm_mma_kernel(
        const float* __restrict__ f1, const float* __restrict__ f2) {
    extern __shared__ __half Ws[];    // [128 n][WST k]
    int br = blockIdx.y;
    const float* __restrict__ feat = br ? f2 : f1;
    const int tid = threadIdx.x;

    {   // copy pre-transposed fp16 W into smem (vectorized)
        const uint4* s = reinterpret_cast<const uint4*>(g_Wh);
        uint4* dsm = reinterpret_cast<uint4*>(Ws);
        #pragma unroll
        for (int i = tid; i < NF * WST * 2 / 16; i += 256) dsm[i] = s[i];
    }
    __syncthreads();

    const int w = tid >> 5, lane = tid & 31;
    const int g = lane >> 2, tg = lane & 3;
    const int base = blockIdx.x * 128;
    const int row0 = base + w * 16 + g;
    const int row1 = row0 + 8;
    const bool v0 = row0 < NN, v1 = row1 < NN;
    const float c0 = v0 ? rsqrtf(fmaxf((float)g_deg_out[br][row0], 1.f)) : 0.f;
    const float c1 = v1 ? rsqrtf(fmaxf((float)g_deg_out[br][row1], 1.f)) : 0.f;

    unsigned a[8][4];
    const float2 z2 = make_float2(0.f, 0.f);
    #pragma unroll
    for (int kc = 0; kc < 8; kc++) {
        int k0 = kc * 16 + tg * 2;
        float2 x0 = v0 ? *reinterpret_cast<const float2*>(&feat[row0 * 128 + k0])     : z2;
        float2 x1 = v1 ? *reinterpret_cast<const float2*>(&feat[row1 * 128 + k0])     : z2;
        float2 x2 = v0 ? *reinterpret_cast<const float2*>(&feat[row0 * 128 + k0 + 8]) : z2;
        float2 x3 = v1 ? *reinterpret_cast<const float2*>(&feat[row1 * 128 + k0 + 8]) : z2;
        a[kc][0] = h2u(__floats2half2_rn(x0.x * c0, x0.y * c0));
        a[kc][1] = h2u(__floats2half2_rn(x1.x * c1, x1.y * c1));
        a[kc][2] = h2u(__floats2half2_rn(x2.x * c0, x2.y * c0));
        a[kc][3] = h2u(__floats2half2_rn(x3.x * c1, x3.y * c1));
    }

    __half* __restrict__ P = g_P[br];
    #pragma unroll
    for (int nt = 0; nt < 16; nt++) {
        float d0 = 0.f, d1 = 0.f, d2 = 0.f, d3 = 0.f;
        const __half* wrow = &Ws[(nt * 8 + g) * WST + tg * 2];
        #pragma unroll
        for (int kc = 0; kc < 8; kc++) {
            unsigned b0 = *reinterpret_cast<const unsigned*>(wrow + kc * 16);
            unsigned b1 = *reinterpret_cast<const unsigned*>(wrow + kc * 16 + 8);
            asm volatile(
                "mma.sync.aligned.m16n8k16.row.col.f32.f16.f16.f32 "
                "{%0,%1,%2,%3}, {%4,%5,%6,%7}, {%8,%9}, {%0,%1,%2,%3};"
                : "+f"(d0), "+f"(d1), "+f"(d2), "+f"(d3)
                : "r"(a[kc][0]), "r"(a[kc][1]), "r"(a[kc][2]), "r"(a[kc][3]),
                  "r"(b0), "r"(b1));
        }
        int col = nt * 8 + tg * 2;
        if (v0) *reinterpret_cast<__half2*>(&P[row0 * 128 + col]) = __floats2half2_rn(d0, d1);
        if (v1) *reinterpret_cast<__half2*>(&P[row1 * 128 + col]) = __floats2half2_rn(d2, d3);
    }
}

// ---------------- gather + epilogue: register accumulator + inline graph counts ----------------
__global__ __launch_bounds__(256) void agg_epilogue_kernel(
        const int* __restrict__ g1, const int* __restrict__ g2,
        const float* __restrict__ bias) {
    int br = blockIdx.y;
    const int* gid = br ? g2 : g1;
    const int w = threadIdx.x >> 5, lane = threadIdx.x & 31;
    const int* __restrict__ off  = g_off[br];
    const int* __restrict__ esrc = g_esrc[br];
    const uint2* __restrict__ Pu = reinterpret_cast<const uint2*>(g_P[br]);
    float* gsum = g_gsum[br];
    int*   gcnt = g_gcnt[br];
    const float4 bv = reinterpret_cast<const float4*>(bias)[lane];

    float4 racc = make_float4(0.f, 0.f, 0.f, 0.f);
    int rcnt = 0;
    int curg = -1;
    const int baseN = blockIdx.x * 256;

    for (int t = 0; t < 32; t++) {
        int node = baseN + t * 8 + w;
        if (node >= NN) break;                      // monotone in t
        int g = gid[node];
        if (g != curg) {
            if (curg >= 0) {
                atomicAdd(&gsum[curg * 128 + lane * 4 + 0], racc.x);
                atomicAdd(&gsum[curg * 128 + lane * 4 + 1], racc.y);
                atomicAdd(&gsum[curg * 128 + lane * 4 + 2], racc.z);
                atomicAdd(&gsum[curg * 128 + lane * 4 + 3], racc.w);
                if (lane == 0) atomicAdd(&gcnt[curg], rcnt);
                racc = make_float4(0.f, 0.f, 0.f, 0.f);
                rcnt = 0;
            }
            curg = g;
        }
        int beg = off[node], end = off[node + 1];
        float ax = 0.f, ay = 0.f, az = 0.f, aw = 0.f;
        int e = beg;
        while (e < end) {
            int cnt = min(32, end - e);
            int sid = (lane < cnt) ? esrc[e + lane] : 0;
            int j = 0;
            for (; j + 4 <= cnt; j += 4) {
                int s0 = __shfl_sync(0xffffffffu, sid, j + 0);
                int s1 = __shfl_sync(0xffffffffu, sid, j + 1);
                int s2 = __shfl_sync(0xffffffffu, sid, j + 2);
                int s3 = __shfl_sync(0xffffffffu, sid, j + 3);
                uint2 v0 = Pu[s0 * 32 + lane];
                uint2 v1 = Pu[s1 * 32 + lane];
                uint2 v2 = Pu[s2 * 32 + lane];
                uint2 v3 = Pu[s3 * 32 + lane];
                #define ACC_V(v) { \
                    const __half2* hp = reinterpret_cast<const __half2*>(&(v)); \
                    float2 fa = __half22float2(hp[0]); \
                    float2 fb = __half22float2(hp[1]); \
                    ax += fa.x; ay += fa.y; az += fb.x; aw += fb.y; }
                ACC_V(v0) ACC_V(v1) ACC_V(v2) ACC_V(v3)
            }
            for (; j < cnt; j++) {
                int s0 = __shfl_sync(0xffffffffu, sid, j);
                uint2 v0 = Pu[s0 * 32 + lane];
                ACC_V(v0)
                #undef ACC_V
            }
            e += cnt;
        }
        float cin = rsqrtf(fmaxf((float)(end - beg), 1.f));
        float hx = ax * cin + bv.x;
        float hy = ay * cin + bv.y;
        float hz = az * cin + bv.z;
        float hw = aw * cin + bv.w;
        float p = hx * hx + hy * hy + hz * hz + hw * hw;
        #pragma unroll
        for (int o = 16; o > 0; o >>= 1) p += __shfl_xor_sync(0xffffffffu, p, o);
        float inv = 1.f / fmaxf(sqrtf(p), 1e-12f);
        racc.x += 1.f / (1.f + __expf(-hx * inv));   // relu(sigmoid)==sigmoid
        racc.y += 1.f / (1.f + __expf(-hy * inv));
        racc.z += 1.f / (1.f + __expf(-hz * inv));
        racc.w += 1.f / (1.f + __expf(-hw * inv));
        rcnt++;
    }
    if (curg >= 0) {
        atomicAdd(&gsum[curg * 128 + lane * 4 + 0], racc.x);
        atomicAdd(&gsum[curg * 128 + lane * 4 + 1], racc.y);
        atomicAdd(&gsum[curg * 128 + lane * 4 + 2], racc.z);
        atomicAdd(&gsum[curg * 128 + lane * 4 + 3], racc.w);
        if (lane == 0) atomicAdd(&gcnt[curg], rcnt);
    }
}

__global__ void final_kernel(const float* __restrict__ Wc, const float* __restrict__ bc,
                             float* __restrict__ out) {
    __shared__ float h1[128], h2[128];
    __shared__ float rsum[2];
    int g = blockIdx.x, t = threadIdx.x;   // 64 threads
    float c1 = fmaxf((float)g_gcnt[0][g], 1.f);
    float c2 = fmaxf((float)g_gcnt[1][g], 1.f);
    for (int k = t; k < 128; k += 64) {
        h1[k] = g_gsum[0][g * 128 + k] / c1;
        h2[k] = g_gsum[1][g * 128 + k] / c2;
    }
    __syncthreads();
    float l1 = bc[t], l2 = bc[t];
    #pragma unroll 4
    for (int k = 0; k < 128; k++) {
        float w = Wc[k * 64 + t];
        l1 = fmaf(h1[k], w, l1);
        l2 = fmaf(h2[k], w, l2);
    }
    float d = l1 - l2 + 1e-6f;
    float sq = d * d;
    for (int o = 16; o > 0; o >>= 1) sq += __shfl_down_sync(0xffffffffu, sq, o);
    if ((t & 31) == 0) rsum[t >> 5] = sq;
    __syncthreads();
    if (t == 0) out[g] = sqrtf(rsum[0] + rsum[1]);
}

// ---------------- launch (fork-join overlap: CSR chain || GEMM) ----------------
extern "C" void kernel_launch(void* const* d_in, const int* in_sizes, int n_in,
                              void* d_out, int out_size) {
    const float* feat1 = (const float*)d_in[0];
    const float* feat2 = (const float*)d_in[1];
    const int* src1 = (const int*)d_in[2];
    const int* dst1 = (const int*)d_in[3];
    const int* gid1 = (const int*)d_in[4];
    const int* src2 = (const int*)d_in[5];
    const int* dst2 = (const int*)d_in[6];
    const int* gid2 = (const int*)d_in[7];
    const float* W  = (const float*)d_in[8];
    const float* b  = (const float*)d_in[9];
    const float* Wc = (const float*)d_in[10];
    const float* bc = (const float*)d_in[11];
    float* out = (float*)d_out;

    const int EB = (NE + 255) / 256;     // 6250
    const int NB = (NN + 255) / 256;     // 391
    const int GB = (NN + 127) / 128;     // 782
    const int SMEM_MMA = NF * WST * 2;   // 34816 B

    // side stream + events for fork-join inside graph capture (host objects,
    // intentionally not destroyed: kernel_launch only runs for correctness +
    // capture; replays execute the captured graph)
    cudaStream_t s2;
    cudaStreamCreateWithFlags(&s2, cudaStreamNonBlocking);
    cudaEvent_t evA, evB;
    cudaEventCreateWithFlags(&evA, cudaEventDisableTiming);
    cudaEventCreateWithFlags(&evB, cudaEventDisableTiming);

    zw_kernel     <<<dim3(NB, 2), 256>>>(W);
    degree_kernel <<<dim3(EB, 2), 256>>>(src1, dst1, src2, dst2);
    cudaEventRecord(evA, 0);

    // CSR chain on side stream (needs deg_in only)
    cudaStreamWaitEvent(s2, evA, 0);
    scan1_kernel  <<<dim3(SCAN_BLOCKS, 2), SCAN_BS, 0, s2>>>();
    scan2_kernel  <<<dim3(1, 2), 256, 0, s2>>>();
    scan3_kernel  <<<dim3(SCAN_BLOCKS, 2), SCAN_BS, 0, s2>>>();
    scatter_kernel<<<dim3(EB, 2), 256, 0, s2>>>(src1, dst1, src2, dst2);
    cudaEventRecord(evB, s2);

    // GEMM on main stream (needs deg_out + W only) — overlaps the CSR chain
    gemm_mma_kernel<<<dim3(GB, 2), 256, SMEM_MMA>>>(feat1, feat2);

    cudaStreamWaitEvent(0, evB, 0);
    agg_epilogue_kernel<<<dim3(NB, 2), 256>>>(gid1, gid2, b);
    final_kernel  <<<NG, 64>>>(Wc, bc, out);
}